// round 1
// baseline (speedup 1.0000x reference)
#include <cuda_runtime.h>
#include <cuda_bf16.h>
#include <cstdint>

#define D      512
#define NWAY   64
#define KSHOT  16
#define MAXQ   8192
#define SA     72   // padded SMEM K-stride (bf16 elems): 144B rows -> conflict-free frag loads

// ---------------- device scratch (no allocation allowed) ----------------
__device__ float          g_smean[NWAY * D];
__device__ float          g_pfp32[NWAY * D];
__device__ __nv_bfloat16  g_proto[NWAY * D];
__device__ float          g_pnorm[NWAY];
__device__ __nv_bfloat16  g_qe[(size_t)MAXQ * D];

// ---------------- mma.sync m16n8k16 bf16 (fp32 accum) ----------------
__device__ __forceinline__ void mma16816(float* c,
                                         uint32_t a0, uint32_t a1, uint32_t a2, uint32_t a3,
                                         uint32_t b0, uint32_t b1) {
    asm volatile(
        "mma.sync.aligned.m16n8k16.row.col.f32.bf16.bf16.f32 "
        "{%0,%1,%2,%3},{%4,%5,%6,%7},{%8,%9},{%0,%1,%2,%3};\n"
        : "+f"(c[0]), "+f"(c[1]), "+f"(c[2]), "+f"(c[3])
        : "r"(a0), "r"(a1), "r"(a2), "r"(a3), "r"(b0), "r"(b1));
}

// ---------------- kernel 1: class means over k_shot ----------------
__global__ void proto_mean_kernel(const float* __restrict__ support) {
    int c = blockIdx.x;
    for (int col = threadIdx.x; col < D; col += blockDim.x) {
        float s = 0.f;
        #pragma unroll
        for (int k = 0; k < KSHOT; k++) s += support[(size_t)(c * KSHOT + k) * D + col];
        g_smean[c * D + col] = s * (1.f / KSHOT);
    }
}

// ---------------- kernel 2: prototypes = smean @ W^T + b ----------------
// block b handles 4 output columns (W rows) for all 64 classes
__global__ void proto_proj_kernel(const float* __restrict__ W, const float* __restrict__ bias) {
    __shared__ float sW[4][D + 8];
    int nb = blockIdx.x * 4;
    for (int i = threadIdx.x; i < 4 * D; i += blockDim.x) {
        int n = i >> 9, k = i & (D - 1);
        sW[n][k] = W[(size_t)(nb + n) * D + k];
    }
    __syncthreads();
    for (int o = threadIdx.x; o < NWAY * 4; o += blockDim.x) {
        int c = o >> 2, nl = o & 3;
        const float* s = g_smean + c * D;
        float acc = 0.f;
        #pragma unroll 8
        for (int k = 0; k < D; k++) acc += s[k] * sW[nl][k];
        acc += bias[nb + nl];
        g_pfp32[c * D + nb + nl] = acc;
        g_proto[c * D + nb + nl] = __float2bfloat16(acc);
    }
}

// ---------------- kernel 3: prototype norms (fp32, exact) ----------------
__global__ void proto_norm_kernel() {
    int c = blockIdx.x;
    float p = 0.f;
    for (int k = threadIdx.x; k < D; k += blockDim.x) {
        float v = g_pfp32[c * D + k];
        p += v * v;
    }
    __shared__ float red[4];
    #pragma unroll
    for (int o = 16; o > 0; o >>= 1) p += __shfl_xor_sync(0xffffffffu, p, o);
    if ((threadIdx.x & 31) == 0) red[threadIdx.x >> 5] = p;
    __syncthreads();
    if (threadIdx.x == 0) g_pnorm[c] = red[0] + red[1] + red[2] + red[3];
}

// ---------------- kernel 4: qe = query @ W^T + b  (bf16 MMA, 128x128 tiles) ----------------
__global__ __launch_bounds__(256) void qe_gemm_kernel(const float* __restrict__ q,
                                                      const float* __restrict__ W,
                                                      const float* __restrict__ bias, int M) {
    __shared__ __nv_bfloat16 sA[128 * SA];
    __shared__ __nv_bfloat16 sB[128 * SA];
    __shared__ float sbias[128];
    int tid = threadIdx.x;
    int m0 = blockIdx.x * 128, n0 = blockIdx.y * 128;
    if (tid < 128) sbias[tid] = bias[n0 + tid];

    float acc[4][4][4];
    #pragma unroll
    for (int a = 0; a < 4; a++)
        #pragma unroll
        for (int b = 0; b < 4; b++)
            #pragma unroll
            for (int c = 0; c < 4; c++) acc[a][b][c] = 0.f;

    int warp = tid >> 5, lane = tid & 31;
    int wm = warp >> 2, wn = warp & 3;   // warp tile: 64(M) x 32(N)
    int g = lane >> 2, t4 = lane & 3;

    for (int kc = 0; kc < D; kc += 64) {
        // load + convert A (query) tile: 128 x 64 f32 -> bf16
        #pragma unroll
        for (int j = 0; j < 8; j++) {
            int idx = tid + j * 256;
            int row = idx >> 4, cv = idx & 15;
            float4 v = make_float4(0.f, 0.f, 0.f, 0.f);
            if (m0 + row < M) v = *(const float4*)(q + (size_t)(m0 + row) * D + kc + cv * 4);
            *(__nv_bfloat162*)(sA + row * SA + cv * 4)     = __floats2bfloat162_rn(v.x, v.y);
            *(__nv_bfloat162*)(sA + row * SA + cv * 4 + 2) = __floats2bfloat162_rn(v.z, v.w);
        }
        // load + convert B (W) tile: 128 x 64
        #pragma unroll
        for (int j = 0; j < 8; j++) {
            int idx = tid + j * 256;
            int row = idx >> 4, cv = idx & 15;
            float4 v = *(const float4*)(W + (size_t)(n0 + row) * D + kc + cv * 4);
            *(__nv_bfloat162*)(sB + row * SA + cv * 4)     = __floats2bfloat162_rn(v.x, v.y);
            *(__nv_bfloat162*)(sB + row * SA + cv * 4 + 2) = __floats2bfloat162_rn(v.z, v.w);
        }
        __syncthreads();

        #pragma unroll
        for (int kk = 0; kk < 64; kk += 16) {
            uint32_t bf[4][2];
            #pragma unroll
            for (int nf = 0; nf < 4; nf++) {
                int n = wn * 32 + nf * 8 + g;
                bf[nf][0] = *(const uint32_t*)(sB + n * SA + kk + t4 * 2);
                bf[nf][1] = *(const uint32_t*)(sB + n * SA + kk + 8 + t4 * 2);
            }
            #pragma unroll
            for (int mf = 0; mf < 4; mf++) {
                int m = wm * 64 + mf * 16;
                uint32_t a0 = *(const uint32_t*)(sA + (m + g) * SA + kk + t4 * 2);
                uint32_t a1 = *(const uint32_t*)(sA + (m + g + 8) * SA + kk + t4 * 2);
                uint32_t a2 = *(const uint32_t*)(sA + (m + g) * SA + kk + 8 + t4 * 2);
                uint32_t a3 = *(const uint32_t*)(sA + (m + g + 8) * SA + kk + 8 + t4 * 2);
                #pragma unroll
                for (int nf = 0; nf < 4; nf++)
                    mma16816(acc[mf][nf], a0, a1, a2, a3, bf[nf][0], bf[nf][1]);
            }
        }
        __syncthreads();
    }

    // epilogue: add bias, store qe as bf16
    #pragma unroll
    for (int mf = 0; mf < 4; mf++) {
        int rr0 = wm * 64 + mf * 16 + g;
        #pragma unroll
        for (int nf = 0; nf < 4; nf++) {
            int cc = wn * 32 + nf * 8 + t4 * 2;
            float b0v = sbias[cc], b1v = sbias[cc + 1];
            float v00 = acc[mf][nf][0] + b0v, v01 = acc[mf][nf][1] + b1v;
            float v10 = acc[mf][nf][2] + b0v, v11 = acc[mf][nf][3] + b1v;
            if (m0 + rr0 < M)
                *(__nv_bfloat162*)(g_qe + (size_t)(m0 + rr0) * D + n0 + cc) = __floats2bfloat162_rn(v00, v01);
            if (m0 + rr0 + 8 < M)
                *(__nv_bfloat162*)(g_qe + (size_t)(m0 + rr0 + 8) * D + n0 + cc) = __floats2bfloat162_rn(v10, v11);
        }
    }
}

// ---------------- kernel 5: dists = ||qe||^2 + ||p||^2 - 2 * qe@p^T ----------------
// block: 64 queries x all 64 classes; query norms computed in-block from bf16 qe tiles
__global__ __launch_bounds__(128) void dist_kernel(float* __restrict__ out, int M) {
    __shared__ __nv_bfloat16 sQ[64 * SA];
    __shared__ __nv_bfloat16 sP[64 * SA];
    __shared__ float sqn[64];
    int tid = threadIdx.x;
    int m0 = blockIdx.x * 64;
    int warp = tid >> 5, lane = tid & 31;
    int g = lane >> 2, t4 = lane & 3;

    float acc[4][2][4];
    #pragma unroll
    for (int a = 0; a < 4; a++)
        #pragma unroll
        for (int b = 0; b < 2; b++)
            #pragma unroll
            for (int c = 0; c < 4; c++) acc[a][b][c] = 0.f;

    float nrm = 0.f;
    int nrow = tid >> 1, nhalf = tid & 1;

    for (int kc = 0; kc < D; kc += 64) {
        __syncthreads();
        #pragma unroll
        for (int j = 0; j < 4; j++) {
            int idx = tid + j * 128;
            int row = idx >> 3, cv = idx & 7;
            uint4 v = make_uint4(0u, 0u, 0u, 0u);
            if (m0 + row < M) v = *(const uint4*)(g_qe + (size_t)(m0 + row) * D + kc + cv * 8);
            *(uint4*)(sQ + row * SA + cv * 8) = v;
            uint4 w = *(const uint4*)(g_proto + (size_t)row * D + kc + cv * 8);
            *(uint4*)(sP + row * SA + cv * 8) = w;
        }
        __syncthreads();

        // per-row query norm partials (fp32 accumulation of bf16 qe)
        const __nv_bfloat162* qrow = (const __nv_bfloat162*)(sQ + nrow * SA + nhalf * 32);
        #pragma unroll
        for (int j = 0; j < 16; j++) {
            float2 f = __bfloat1622float2(qrow[j]);
            nrm += f.x * f.x + f.y * f.y;
        }

        #pragma unroll
        for (int kk = 0; kk < 64; kk += 16) {
            uint32_t bf[2][2];
            #pragma unroll
            for (int nf = 0; nf < 2; nf++) {
                int n = warp * 16 + nf * 8 + g;
                bf[nf][0] = *(const uint32_t*)(sP + n * SA + kk + t4 * 2);
                bf[nf][1] = *(const uint32_t*)(sP + n * SA + kk + 8 + t4 * 2);
            }
            #pragma unroll
            for (int mf = 0; mf < 4; mf++) {
                int m = mf * 16;
                uint32_t a0 = *(const uint32_t*)(sQ + (m + g) * SA + kk + t4 * 2);
                uint32_t a1 = *(const uint32_t*)(sQ + (m + g + 8) * SA + kk + t4 * 2);
                uint32_t a2 = *(const uint32_t*)(sQ + (m + g) * SA + kk + 8 + t4 * 2);
                uint32_t a3 = *(const uint32_t*)(sQ + (m + g + 8) * SA + kk + 8 + t4 * 2);
                #pragma unroll
                for (int nf = 0; nf < 2; nf++)
                    mma16816(acc[mf][nf], a0, a1, a2, a3, bf[nf][0], bf[nf][1]);
            }
        }
    }

    float tot = nrm + __shfl_xor_sync(0xffffffffu, nrm, 1);
    if (!nhalf) sqn[nrow] = tot;
    __syncthreads();

    #pragma unroll
    for (int mf = 0; mf < 4; mf++) {
        int r0 = mf * 16 + g;
        #pragma unroll
        for (int nf = 0; nf < 2; nf++) {
            int cc = warp * 16 + nf * 8 + t4 * 2;
            float pn0 = g_pnorm[cc], pn1 = g_pnorm[cc + 1];
            if (m0 + r0 < M) {
                float qn0 = sqn[r0];
                float2 o;
                o.x = qn0 + pn0 - 2.f * acc[mf][nf][0];
                o.y = qn0 + pn1 - 2.f * acc[mf][nf][1];
                *(float2*)(out + (size_t)(m0 + r0) * NWAY + cc) = o;
            }
            if (m0 + r0 + 8 < M) {
                float qn1 = sqn[r0 + 8];
                float2 o;
                o.x = qn1 + pn0 - 2.f * acc[mf][nf][2];
                o.y = qn1 + pn1 - 2.f * acc[mf][nf][3];
                *(float2*)(out + (size_t)(m0 + r0 + 8) * NWAY + cc) = o;
            }
        }
    }
}

// ---------------- launch ----------------
extern "C" void kernel_launch(void* const* d_in, const int* in_sizes, int n_in,
                              void* d_out, int out_size) {
    const float* support = (const float*)d_in[0];
    const float* query   = (const float*)d_in[1];
    const float* W       = (const float*)d_in[2];
    const float* bias    = (const float*)d_in[3];
    int M = in_sizes[1] / D;
    if (M > MAXQ) M = MAXQ;
    float* out = (float*)d_out;

    proto_mean_kernel<<<NWAY, 128>>>(support);
    proto_proj_kernel<<<D / 4, 128>>>(W, bias);
    proto_norm_kernel<<<NWAY, 128>>>();
    qe_gemm_kernel<<<dim3((M + 127) / 128, 4), 256>>>(query, W, bias, M);
    dist_kernel<<<(M + 63) / 64, 128>>>(out, M);
}

// round 2
// speedup vs baseline: 1.2022x; 1.2022x over previous
#include <cuda_runtime.h>
#include <cuda_bf16.h>
#include <cstdint>

#define D      512
#define NWAY   64
#define KSHOT  16
#define BM     64    // query rows per block
#define SQ     520   // resident tile row stride (bf16): 1040B -> conflict-free frag loads
#define SB     72    // W tile stride (bf16): 144B rows
#define SE     136   // qe staging stride (bf16): 272B rows

// ---------------- device scratch ----------------
__device__ float          g_smean[NWAY * D];
__device__ float          g_pfp32[NWAY * D];
__device__ __nv_bfloat16  g_proto[NWAY * D];
__device__ float          g_pnorm[NWAY];
__device__ __nv_bfloat16  g_Wbf[D * D];

// ---------------- helpers ----------------
__device__ __forceinline__ void mma16816(float* c,
                                         uint32_t a0, uint32_t a1, uint32_t a2, uint32_t a3,
                                         uint32_t b0, uint32_t b1) {
    asm volatile(
        "mma.sync.aligned.m16n8k16.row.col.f32.bf16.bf16.f32 "
        "{%0,%1,%2,%3},{%4,%5,%6,%7},{%8,%9},{%0,%1,%2,%3};\n"
        : "+f"(c[0]), "+f"(c[1]), "+f"(c[2]), "+f"(c[3])
        : "r"(a0), "r"(a1), "r"(a2), "r"(a3), "r"(b0), "r"(b1));
}

__device__ __forceinline__ void cp_async16(void* smem, const void* gmem) {
    uint32_t s = (uint32_t)__cvta_generic_to_shared(smem);
    asm volatile("cp.async.cg.shared.global [%0], [%1], 16;\n" :: "r"(s), "l"(gmem));
}
#define CP_COMMIT() asm volatile("cp.async.commit_group;\n")
#define CP_WAIT(n)  asm volatile("cp.async.wait_group %0;\n" :: "n"(n))

// ---------------- prep 1: W f32->bf16 convert  +  class means ----------------
__global__ void prep_kernel(const float* __restrict__ W, const float* __restrict__ support) {
    int b = blockIdx.x;
    if (b < 256) {
        // W convert: 262144 elems / 256 blocks = 1024 per block; 4 per thread
        int base = b * 1024 + threadIdx.x * 4;
        float4 v = *(const float4*)(W + base);
        *(__nv_bfloat162*)(g_Wbf + base)     = __floats2bfloat162_rn(v.x, v.y);
        *(__nv_bfloat162*)(g_Wbf + base + 2) = __floats2bfloat162_rn(v.z, v.w);
    } else {
        int c = b - 256;           // class 0..63
        for (int col = threadIdx.x; col < D; col += blockDim.x) {
            float s = 0.f;
            #pragma unroll
            for (int k = 0; k < KSHOT; k++) s += support[(size_t)(c * KSHOT + k) * D + col];
            g_smean[c * D + col] = s * (1.f / KSHOT);
        }
    }
}

// ---------------- prep 2: prototypes = smean @ W^T + b ----------------
__global__ void proto_proj_kernel(const float* __restrict__ W, const float* __restrict__ bias) {
    __shared__ float sW[4][D + 8];
    int nb = blockIdx.x * 4;
    for (int i = threadIdx.x; i < 4 * D; i += blockDim.x) {
        int n = i >> 9, k = i & (D - 1);
        sW[n][k] = W[(size_t)(nb + n) * D + k];
    }
    __syncthreads();
    for (int o = threadIdx.x; o < NWAY * 4; o += blockDim.x) {
        int c = o >> 2, nl = o & 3;
        const float* s = g_smean + c * D;
        float acc = 0.f;
        #pragma unroll 8
        for (int k = 0; k < D; k++) acc += s[k] * sW[nl][k];
        acc += bias[nb + nl];
        g_pfp32[c * D + nb + nl] = acc;
        g_proto[c * D + nb + nl] = __float2bfloat16(acc);
    }
}

// ---------------- prep 3: prototype norms (fp32 exact) ----------------
__global__ void proto_norm_kernel() {
    int c = blockIdx.x;
    float p = 0.f;
    for (int k = threadIdx.x; k < D; k += blockDim.x) {
        float v = g_pfp32[c * D + k];
        p += v * v;
    }
    __shared__ float red[4];
    #pragma unroll
    for (int o = 16; o > 0; o >>= 1) p += __shfl_xor_sync(0xffffffffu, p, o);
    if ((threadIdx.x & 31) == 0) red[threadIdx.x >> 5] = p;
    __syncthreads();
    if (threadIdx.x == 0) g_pnorm[c] = red[0] + red[1] + red[2] + red[3];
}

// ---------------- fused main kernel ----------------
// block = 64 query rows x all 64 classes. Query tile + prototypes resident in SMEM.
// Loop over 4 chunks of 128 W-rows: qe chunk via MMA (W streamed cp.async double-buffered),
// stage qe chunk bf16 in SMEM, accumulate query norms + distance MMA. No global qe.
#define OFF_SQ    0
#define OFF_SP    66560
#define OFF_SB    133120
#define OFF_SE    169984
#define OFF_BIAS  187392
#define OFF_SQN   187904
#define OFF_SPN   188160
#define SMEM_TOT  188416

__device__ __forceinline__ void load_w_tile(__nv_bfloat16* dst, const __nv_bfloat16* src, int tid) {
    #pragma unroll
    for (int j = 0; j < 4; j++) {
        int i = tid + j * 256;
        int row = i >> 3, c = i & 7;
        cp_async16(dst + row * SB + c * 8, src + (size_t)row * D + c * 8);
    }
    CP_COMMIT();
}

__global__ __launch_bounds__(256, 1) void fused_kernel(const float* __restrict__ q,
                                                       const float* __restrict__ bias,
                                                       float* __restrict__ out, int M) {
    extern __shared__ char sm[];
    __nv_bfloat16* sQ = (__nv_bfloat16*)(sm + OFF_SQ);
    __nv_bfloat16* sP = (__nv_bfloat16*)(sm + OFF_SP);
    __nv_bfloat16* sB = (__nv_bfloat16*)(sm + OFF_SB);
    __nv_bfloat16* sE = (__nv_bfloat16*)(sm + OFF_SE);
    float* sbias = (float*)(sm + OFF_BIAS);
    float* sqn   = (float*)(sm + OFF_SQN);
    float* spn   = (float*)(sm + OFF_SPN);

    int tid = threadIdx.x;
    int m0 = blockIdx.x * BM;
    int warp = tid >> 5, lane = tid & 31;
    int g = lane >> 2, t4 = lane & 3;
    int wm1 = warp >> 2, wn1 = warp & 3;   // qe GEMM: warp tile 32(M) x 32(N)
    int wm2 = warp >> 2, wn2 = warp & 3;   // dist GEMM: warp tile 32(M) x 16(N)

    // ---- residents: query tile (f32->bf16) and prototypes ----
    for (int i = tid; i < BM * D / 4; i += 256) {
        int row = i >> 7, c4 = i & 127;
        float4 v = make_float4(0.f, 0.f, 0.f, 0.f);
        if (m0 + row < M) v = *(const float4*)(q + (size_t)(m0 + row) * D + c4 * 4);
        *(__nv_bfloat162*)(sQ + row * SQ + c4 * 4)     = __floats2bfloat162_rn(v.x, v.y);
        *(__nv_bfloat162*)(sQ + row * SQ + c4 * 4 + 2) = __floats2bfloat162_rn(v.z, v.w);
    }
    for (int i = tid; i < NWAY * D / 8; i += 256) {
        int row = i >> 6, c8 = i & 63;
        *(uint4*)(sP + row * SQ + c8 * 8) = *(const uint4*)(g_proto + (size_t)row * D + c8 * 8);
    }
    if (tid < NWAY) spn[tid] = g_pnorm[tid];

    float dacc[2][2][4];
    #pragma unroll
    for (int a = 0; a < 2; a++)
        #pragma unroll
        for (int b = 0; b < 2; b++)
            #pragma unroll
            for (int c = 0; c < 4; c++) dacc[a][b][c] = 0.f;
    float nrm = 0.f;

    __syncthreads();

    for (int nc = 0; nc < 4; nc++) {
        int n0 = nc * 128;
        if (tid < 128) sbias[tid] = bias[n0 + tid];

        float qacc[2][4][4];
        #pragma unroll
        for (int a = 0; a < 2; a++)
            #pragma unroll
            for (int b = 0; b < 4; b++)
                #pragma unroll
                for (int c = 0; c < 4; c++) qacc[a][b][c] = 0.f;

        // ---- qe chunk GEMM: K=512, cp.async double-buffered W tiles ----
        load_w_tile(sB, g_Wbf + (size_t)n0 * D, tid);
        #pragma unroll 1
        for (int kci = 0; kci < 8; kci++) {
            if (kci < 7) {
                load_w_tile(sB + ((kci + 1) & 1) * 128 * SB,
                            g_Wbf + (size_t)n0 * D + (kci + 1) * 64, tid);
                CP_WAIT(1);
            } else {
                CP_WAIT(0);
            }
            __syncthreads();
            const __nv_bfloat16* bb = sB + (kci & 1) * 128 * SB;
            int kc = kci * 64;
            #pragma unroll
            for (int kk = 0; kk < 64; kk += 16) {
                uint32_t bf[4][2];
                #pragma unroll
                for (int nf = 0; nf < 4; nf++) {
                    int n = wn1 * 32 + nf * 8 + g;
                    bf[nf][0] = *(const uint32_t*)(bb + n * SB + kk + t4 * 2);
                    bf[nf][1] = *(const uint32_t*)(bb + n * SB + kk + 8 + t4 * 2);
                }
                #pragma unroll
                for (int mf = 0; mf < 2; mf++) {
                    int m = wm1 * 32 + mf * 16;
                    uint32_t a0 = *(const uint32_t*)(sQ + (m + g) * SQ + kc + kk + t4 * 2);
                    uint32_t a1 = *(const uint32_t*)(sQ + (m + g + 8) * SQ + kc + kk + t4 * 2);
                    uint32_t a2 = *(const uint32_t*)(sQ + (m + g) * SQ + kc + kk + 8 + t4 * 2);
                    uint32_t a3 = *(const uint32_t*)(sQ + (m + g + 8) * SQ + kc + kk + 8 + t4 * 2);
                    #pragma unroll
                    for (int nf = 0; nf < 4; nf++)
                        mma16816(qacc[mf][nf], a0, a1, a2, a3, bf[nf][0], bf[nf][1]);
                }
            }
            __syncthreads();
        }

        // ---- stage qe chunk (bias added) as bf16 in sE ----
        #pragma unroll
        for (int mf = 0; mf < 2; mf++) {
            int r = wm1 * 32 + mf * 16 + g;
            #pragma unroll
            for (int nf = 0; nf < 4; nf++) {
                int c = wn1 * 32 + nf * 8 + t4 * 2;
                float b0v = sbias[c], b1v = sbias[c + 1];
                *(__nv_bfloat162*)(sE + r * SE + c) =
                    __floats2bfloat162_rn(qacc[mf][nf][0] + b0v, qacc[mf][nf][1] + b1v);
                *(__nv_bfloat162*)(sE + (r + 8) * SE + c) =
                    __floats2bfloat162_rn(qacc[mf][nf][2] + b0v, qacc[mf][nf][3] + b1v);
            }
        }
        __syncthreads();

        // ---- query-embedding norm partials (fp32 over bf16 qe) ----
        {
            const __nv_bfloat162* er = (const __nv_bfloat162*)(sE + (tid >> 2) * SE + (tid & 3) * 32);
            #pragma unroll
            for (int j = 0; j < 16; j++) {
                float2 f = __bfloat1622float2(er[j]);
                nrm += f.x * f.x + f.y * f.y;
            }
        }

        // ---- distance MMA: dacc += qe_chunk @ proto_chunk^T ----
        #pragma unroll
        for (int kk = 0; kk < 128; kk += 16) {
            uint32_t bf[2][2];
            #pragma unroll
            for (int nf = 0; nf < 2; nf++) {
                int n = wn2 * 16 + nf * 8 + g;
                bf[nf][0] = *(const uint32_t*)(sP + n * SQ + n0 + kk + t4 * 2);
                bf[nf][1] = *(const uint32_t*)(sP + n * SQ + n0 + kk + 8 + t4 * 2);
            }
            #pragma unroll
            for (int mf = 0; mf < 2; mf++) {
                int m = wm2 * 32 + mf * 16;
                uint32_t a0 = *(const uint32_t*)(sE + (m + g) * SE + kk + t4 * 2);
                uint32_t a1 = *(const uint32_t*)(sE + (m + g + 8) * SE + kk + t4 * 2);
                uint32_t a2 = *(const uint32_t*)(sE + (m + g) * SE + kk + 8 + t4 * 2);
                uint32_t a3 = *(const uint32_t*)(sE + (m + g + 8) * SE + kk + 8 + t4 * 2);
                #pragma unroll
                for (int nf = 0; nf < 2; nf++)
                    mma16816(dacc[mf][nf], a0, a1, a2, a3, bf[nf][0], bf[nf][1]);
            }
        }
        __syncthreads();   // before next nc overwrites sE / sbias
    }

    // ---- epilogue: reduce norms, combine, store ----
    nrm += __shfl_xor_sync(0xffffffffu, nrm, 1);
    nrm += __shfl_xor_sync(0xffffffffu, nrm, 2);
    if ((tid & 3) == 0) sqn[tid >> 2] = nrm;
    __syncthreads();

    #pragma unroll
    for (int mf = 0; mf < 2; mf++) {
        int r = wm2 * 32 + mf * 16 + g;
        #pragma unroll
        for (int nf = 0; nf < 2; nf++) {
            int c = wn2 * 16 + nf * 8 + t4 * 2;
            float pn0 = spn[c], pn1 = spn[c + 1];
            if (m0 + r < M) {
                float qn = sqn[r];
                float2 o;
                o.x = qn + pn0 - 2.f * dacc[mf][nf][0];
                o.y = qn + pn1 - 2.f * dacc[mf][nf][1];
                *(float2*)(out + (size_t)(m0 + r) * NWAY + c) = o;
            }
            if (m0 + r + 8 < M) {
                float qn = sqn[r + 8];
                float2 o;
                o.x = qn + pn0 - 2.f * dacc[mf][nf][2];
                o.y = qn + pn1 - 2.f * dacc[mf][nf][3];
                *(float2*)(out + (size_t)(m0 + r + 8) * NWAY + c) = o;
            }
        }
    }
}

// ---------------- launch ----------------
extern "C" void kernel_launch(void* const* d_in, const int* in_sizes, int n_in,
                              void* d_out, int out_size) {
    const float* support = (const float*)d_in[0];
    const float* query   = (const float*)d_in[1];
    const float* W       = (const float*)d_in[2];
    const float* bias    = (const float*)d_in[3];
    int M = in_sizes[1] / D;
    float* out = (float*)d_out;

    cudaFuncSetAttribute(fused_kernel, cudaFuncAttributeMaxDynamicSharedMemorySize, SMEM_TOT);

    prep_kernel<<<256 + NWAY, 256>>>(W, support);
    proto_proj_kernel<<<D / 4, 128>>>(W, bias);
    proto_norm_kernel<<<NWAY, 128>>>();
    fused_kernel<<<(M + BM - 1) / BM, 256, SMEM_TOT>>>(query, bias, out, M);
}